// round 1
// baseline (speedup 1.0000x reference)
#include <cuda_runtime.h>
#include <cstdint>

// Problem constants
#define B_ 4
#define H_ 16
#define S_ 1024
#define D_ 64

// 1 => JAX jax_threefry_partitionable=True (default since JAX 0.4.36):
//      bits[i] = x0^x1 of threefry((0,42),(0,i))
// 0 => legacy path: counters split in halves, bits[i]=out0 (i<n/2) / out1
#define JAX_PARTITIONABLE 1

#define NTOT   ((size_t)B_ * H_ * S_ * S_)   // 2^26 mask bits
#define NWORDS (NTOT / 32)                   // 2^21 uint32 words

__device__ uint32_t g_mask[NWORDS];          // 8 MB scratch (static, allowed)

// ---------------------------------------------------------------------------
// Threefry-2x32 (20 rounds), matches jax/_src/prng.py
// ---------------------------------------------------------------------------
__device__ __forceinline__ void threefry2x32(uint32_t k0, uint32_t k1,
                                             uint32_t& x0, uint32_t& x1) {
    uint32_t ks2 = 0x1BD11BDAu ^ k0 ^ k1;
    x0 += k0; x1 += k1;
#define TF_RND(r) { x0 += x1; x1 = __funnelshift_l(x1, x1, (r)); x1 ^= x0; }
    TF_RND(13) TF_RND(15) TF_RND(26) TF_RND(6)
    x0 += k1;  x1 += ks2 + 1u;
    TF_RND(17) TF_RND(29) TF_RND(16) TF_RND(24)
    x0 += ks2; x1 += k0 + 2u;
    TF_RND(13) TF_RND(15) TF_RND(26) TF_RND(6)
    x0 += k0;  x1 += k1 + 3u;
    TF_RND(17) TF_RND(29) TF_RND(16) TF_RND(24)
    x0 += k1;  x1 += ks2 + 4u;
    TF_RND(13) TF_RND(15) TF_RND(26) TF_RND(6)
    x0 += ks2; x1 += k0 + 5u;
#undef TF_RND
}

// keep  <=>  uniform(bits) < 0.9f  <=>  (bits>>9) < 0x733333  <=>  bits < 0xE6666600
#define KEEP_THRESH 0xE6666600u

// ---------------------------------------------------------------------------
// Mask precompute: one 32-bit mask word per thread
// ---------------------------------------------------------------------------
__global__ void __launch_bounds__(256) mask_kernel() {
    uint32_t t = blockIdx.x * 256u + threadIdx.x;       // [0, NWORDS) or [0, NWORDS/2)
#if JAX_PARTITIONABLE
    uint32_t base = t * 32u;
    uint32_t w = 0u;
#pragma unroll 4
    for (int b = 0; b < 32; b++) {
        uint32_t x0 = 0u, x1 = base + (uint32_t)b;      // (hi, lo) of 64-bit iota
        threefry2x32(0u, 42u, x0, x1);
        uint32_t bits = x0 ^ x1;
        w |= (bits < KEEP_THRESH ? 1u : 0u) << b;
    }
    g_mask[t] = w;
#else
    // legacy: counters [0..n) split into halves; (out0,out1)=threefry(key, i, i+n/2)
    const uint32_t HALF = (uint32_t)(NTOT / 2);
    uint32_t base = t * 32u;                            // t in [0, NWORDS/2)
    uint32_t w0 = 0u, w1 = 0u;
#pragma unroll 4
    for (int b = 0; b < 32; b++) {
        uint32_t x0 = base + (uint32_t)b;
        uint32_t x1 = x0 + HALF;
        threefry2x32(0u, 42u, x0, x1);
        w0 |= (x0 < KEEP_THRESH ? 1u : 0u) << b;
        w1 |= (x1 < KEEP_THRESH ? 1u : 0u) << b;
    }
    g_mask[t] = w0;
    g_mask[t + NWORDS / 2] = w1;
#endif
}

// ---------------------------------------------------------------------------
// Flash attention, fp32, 64x64 tiles, 256 threads, 4x4 strided micro-tiles
// ---------------------------------------------------------------------------
#define QT 64
#define STRIDE 68        // padded float stride (conflict mitigation + 16B align)
#define ST4 17           // STRIDE/4

__global__ void __launch_bounds__(256, 2)
attn_kernel(const float* __restrict__ Q, const float* __restrict__ K,
            const float* __restrict__ V, const uint32_t* __restrict__ scale_ptr,
            float* __restrict__ O) {
    extern __shared__ float sm[];
    float* Qs = sm;                      // QT x STRIDE (pre-scaled by scale_factor)
    float* Ks = sm + QT * STRIDE;
    float* Vs = sm + 2 * QT * STRIDE;
    float* Ps = sm + 3 * QT * STRIDE;

    const int tid = threadIdx.x;
    const int bh  = blockIdx.y;          // b*H + h
    const int qb  = blockIdx.x * QT;

    // scale_factor may arrive as int32(8) or float32(8.0); decode either
    uint32_t sw = *scale_ptr;
    float scale = (sw & 0x7f800000u) ? __uint_as_float(sw) : (float)(int)sw;

    const float* Qp = Q + ((size_t)bh * S_ + qb) * D_;
    const float* Kp = K + (size_t)bh * S_ * D_;
    const float* Vp = V + (size_t)bh * S_ * D_;

    // Load Q tile (scaled)
    for (int e = tid; e < QT * D_ / 4; e += 256) {
        int r = e >> 4, c = e & 15;
        float4 v = reinterpret_cast<const float4*>(Qp)[e];
        v.x *= scale; v.y *= scale; v.z *= scale; v.w *= scale;
        *reinterpret_cast<float4*>(&Qs[r * STRIDE + c * 4]) = v;
    }

    const int ty = tid >> 4;             // 0..15 (row group)
    const int tx = tid & 15;             // 0..15 (col group)

    float acc[4][4];
    float mrow[4], lrow[4];
#pragma unroll
    for (int i = 0; i < 4; i++) {
        mrow[i] = -1e30f; lrow[i] = 0.f;
#pragma unroll
        for (int j = 0; j < 4; j++) acc[i][j] = 0.f;
    }

    __syncthreads();

    for (int kt = 0; kt < S_ / QT; kt++) {
        // Load K, V tiles
        const float* Kt = Kp + (size_t)kt * QT * D_;
        const float* Vt = Vp + (size_t)kt * QT * D_;
        for (int e = tid; e < QT * D_ / 4; e += 256) {
            int r = e >> 4, c = e & 15;
            *reinterpret_cast<float4*>(&Ks[r * STRIDE + c * 4]) =
                reinterpret_cast<const float4*>(Kt)[e];
            *reinterpret_cast<float4*>(&Vs[r * STRIDE + c * 4]) =
                reinterpret_cast<const float4*>(Vt)[e];
        }
        __syncthreads();

        // ---- scores: s[i][j] = Qs[ty+16i] . Ks[tx+16j] (already scaled) ----
        float s[4][4];
#pragma unroll
        for (int i = 0; i < 4; i++)
#pragma unroll
            for (int j = 0; j < 4; j++) s[i][j] = 0.f;

        const float4* Qs4 = reinterpret_cast<const float4*>(Qs);
        const float4* Ks4 = reinterpret_cast<const float4*>(Ks);
#pragma unroll
        for (int c = 0; c < 16; c++) {
            float4 q4[4], k4[4];
#pragma unroll
            for (int i = 0; i < 4; i++) q4[i] = Qs4[(ty + 16 * i) * ST4 + c];
#pragma unroll
            for (int j = 0; j < 4; j++) k4[j] = Ks4[(tx + 16 * j) * ST4 + c];
#pragma unroll
            for (int i = 0; i < 4; i++)
#pragma unroll
                for (int j = 0; j < 4; j++) {
                    s[i][j] += q4[i].x * k4[j].x;
                    s[i][j] += q4[i].y * k4[j].y;
                    s[i][j] += q4[i].z * k4[j].z;
                    s[i][j] += q4[i].w * k4[j].w;
                }
        }

        // ---- online softmax + dropout, per row ----
#pragma unroll
        for (int i = 0; i < 4; i++) {
            float rmax = fmaxf(fmaxf(s[i][0], s[i][1]), fmaxf(s[i][2], s[i][3]));
#pragma unroll
            for (int o = 1; o < 16; o <<= 1)
                rmax = fmaxf(rmax, __shfl_xor_sync(0xffffffffu, rmax, o));
            float mnew = fmaxf(mrow[i], rmax);
            float corr = __expf(mrow[i] - mnew);
            mrow[i] = mnew;

            float psum = 0.f;
#pragma unroll
            for (int j = 0; j < 4; j++) {
                s[i][j] = __expf(s[i][j] - mnew);
                psum += s[i][j];
            }
#pragma unroll
            for (int o = 1; o < 16; o <<= 1)
                psum += __shfl_xor_sync(0xffffffffu, psum, o);

            lrow[i] = lrow[i] * corr + psum;
#pragma unroll
            for (int j = 0; j < 4; j++) acc[i][j] *= corr;

            // dropout: bit index = ((bh*S + qrow)*S + kt*64 + (tx+16j))
            size_t bitbase = ((size_t)bh * S_ + (size_t)(qb + ty + 16 * i)) * S_
                             + (size_t)kt * QT;
            const uint32_t* mp = g_mask + (bitbase >> 5);
            uint32_t lo = mp[0], hi = mp[1];
            if (!((lo >> tx)        & 1u)) s[i][0] = 0.f;
            if (!((lo >> (tx + 16)) & 1u)) s[i][1] = 0.f;
            if (!((hi >> tx)        & 1u)) s[i][2] = 0.f;
            if (!((hi >> (tx + 16)) & 1u)) s[i][3] = 0.f;

#pragma unroll
            for (int j = 0; j < 4; j++)
                Ps[(ty + 16 * i) * STRIDE + tx + 16 * j] = s[i][j];
        }
        __syncthreads();

        // ---- PV: acc[i][j] += sum_k Ps[row_i][k] * Vs[k][col_j] ----
#pragma unroll 4
        for (int k = 0; k < QT; k++) {
            float b0 = Vs[k * STRIDE + tx];
            float b1 = Vs[k * STRIDE + tx + 16];
            float b2 = Vs[k * STRIDE + tx + 32];
            float b3 = Vs[k * STRIDE + tx + 48];
#pragma unroll
            for (int i = 0; i < 4; i++) {
                float a = Ps[(ty + 16 * i) * STRIDE + k];
                acc[i][0] += a * b0;
                acc[i][1] += a * b1;
                acc[i][2] += a * b2;
                acc[i][3] += a * b3;
            }
        }
        __syncthreads();
    }

    // ---- epilogue: O = acc / (l * 0.9) ----
    float* Op = O + ((size_t)bh * S_ + qb) * D_;
#pragma unroll
    for (int i = 0; i < 4; i++) {
        float inv = 1.0f / (lrow[i] * 0.9f);
#pragma unroll
        for (int j = 0; j < 4; j++)
            Op[(ty + 16 * i) * D_ + tx + 16 * j] = acc[i][j] * inv;
    }
}

// ---------------------------------------------------------------------------
extern "C" void kernel_launch(void* const* d_in, const int* in_sizes, int n_in,
                              void* d_out, int out_size) {
    (void)in_sizes; (void)n_in; (void)out_size;
    const float*    Q  = (const float*)d_in[0];
    const float*    K  = (const float*)d_in[1];
    const float*    V  = (const float*)d_in[2];
    const uint32_t* SC = (const uint32_t*)d_in[3];
    float*          O  = (float*)d_out;

#if JAX_PARTITIONABLE
    mask_kernel<<<NWORDS / 256, 256>>>();
#else
    mask_kernel<<<(NWORDS / 2) / 256, 256>>>();
#endif

    static const size_t smem = 4 * QT * STRIDE * sizeof(float);  // 69632 B
    cudaFuncSetAttribute(attn_kernel,
                         cudaFuncAttributeMaxDynamicSharedMemorySize, (int)smem);
    dim3 grid(S_ / QT, B_ * H_);
    attn_kernel<<<grid, 256, smem>>>(Q, K, V, SC, O);
}